// round 13
// baseline (speedup 1.0000x reference)
#include <cuda_runtime.h>
#include <math.h>

#define BSZ    16
#define KNEG   65536
#define KP1    65537u
#define NDIM   128
#define NDATA  1000000
#define INV_T  (1.0f / 0.07f)
#define EMA_M  0.5f

#define LOGITS       (BSZ * 65537)            // 1,048,592
#define NPHASE       16
#define RPP          (NDATA / NPHASE)         // 62,500 rows per phase window
#define PW4          ((size_t)RPP * NDIM / 4) // 2,000,000 float4 per window
#define BPP          2176                     // blocks per group
#define TOTBLK       (NPHASE * BPP)           // 34,816
#define CAPB         131072                   // bin capacity (entries)

#define OUT_LZ_OFF   ((size_t)LOGITS)
#define OUT_MEM_OFF  ((size_t)2 * LOGITS)
#define N4_MEM       ((size_t)NDATA * NDIM / 4)     // 32,000,000
#define N4_SCALE     ((size_t)2 * LOGITS / 4)       // 524,296 (exact)

#define BIN_BLKS     4097u
#define FIN_BLKS     592u
#define FIN_STRIDE   ((size_t)FIN_BLKS * 256)

__device__ double   g_sum;              // zero-init; reset by k_finish each replay
__device__ unsigned g_done;
__device__ unsigned g_bcnt[NPHASE];     // per-phase entry counts
__device__ uint2    g_ent[(size_t)NPHASE * CAPB];   // 16 MB entry store

// ---------------------------------------------------------------------------
// Pass 1: bin every logit by memory-row phase.  Block-aggregated smem counts
// -> 16 global atomics per block.  Entry = { (b<<20)|row , k }.
// ---------------------------------------------------------------------------
__global__ void __launch_bounds__(256) k_bin(
    const float* __restrict__ x, const float* __restrict__ z,
    const float* __restrict__ mem, const int* __restrict__ y,
    const int* __restrict__ idx, float* __restrict__ out)
{
    __shared__ unsigned s_cnt[NPHASE];
    __shared__ unsigned s_base[NPHASE];
    if (threadIdx.x < NPHASE) s_cnt[threadIdx.x] = 0;
    __syncthreads();

    const unsigned t = blockIdx.x * 256u + threadIdx.x;
    const bool valid = t < (unsigned)LOGITS;

    unsigned b = 0, k = 0, bin = 0, lslot = 0;
    int row = 0;
    if (valid) {
        if (t < BSZ) { b = t; k = 0; row = __ldg(&y[b]); }
        else {
            const unsigned u = t - BSZ;
            b = u >> 16;
            k = (u & 65535u) + 1u;
            row = __ldg(&idx[u]);
        }
        bin   = (unsigned)row / RPP;
        lslot = atomicAdd(&s_cnt[bin], 1u);
    }
    __syncthreads();
    if (threadIdx.x < NPHASE && s_cnt[threadIdx.x])
        s_base[threadIdx.x] = atomicAdd(&g_bcnt[threadIdx.x], s_cnt[threadIdx.x]);
    __syncthreads();

    if (valid) {
        const unsigned slot = s_base[bin] + lslot;
        if (slot < CAPB) {
            g_ent[(size_t)bin * CAPB + slot] = make_uint2((b << 20) | (unsigned)row, k);
        } else {
            // capacity overflow fallback (never for this input): compute inline
            const float* w = mem + (size_t)row * NDIM;
            float dx = 0.0f, dz = 0.0f;
            for (int i = 0; i < NDIM; i++) {
                const float wv = __ldg(w + i);
                dx += wv * __ldg(&x[b * NDIM + i]);
                dz += wv * __ldg(&z[b * NDIM + i]);
            }
            const float lx = expf(dx * INV_T);
            const float lz = expf(dz * INV_T);
            out[(size_t)b * KP1 + k]              = lx;
            out[OUT_LZ_OFF + (size_t)b * KP1 + k] = lz;
            atomicAdd(&g_sum, (double)lx);
        }
    }

#if __CUDA_ARCH__ >= 900
    cudaTriggerProgrammaticLaunchCompletion();
#endif
}

// ---------------------------------------------------------------------------
// Pass 2 (wraparound lag): group g copies window g (cached loads seed L2)
// and gathers bin (g+15)%16 — copied by the immediately preceding group,
// so its rows are L2-hot.  Group 0 gathers bin 15 cold (small, one-off).
// Last block of each group loops to absorb counts beyond the slot budget.
// ---------------------------------------------------------------------------
__global__ void __launch_bounds__(256) k_main(
    const float* __restrict__ x, const float* __restrict__ z,
    const float* __restrict__ mem, float* __restrict__ out)
{
#if __CUDA_ARCH__ >= 900
    cudaGridDependencySynchronize();   // all k_bin entries visible
#endif

    const unsigned grp_g = blockIdx.x / BPP;       // 0..15
    const unsigned lblk  = blockIdx.x - grp_g * BPP;
    const int warp = threadIdx.x >> 5;
    const int lane = threadIdx.x & 31;
    const int grp  = lane >> 3;
    const int li   = lane & 7;

    __shared__ double s_part[8];

    // ---- copy window grp_g (cached loads -> window lands in L2) ----
    {
        const size_t wbeg = (size_t)grp_g * PW4;
        const size_t wend = wbeg + PW4;
        const float4* src = (const float4*)mem;
        float4*       dst = (float4*)(out + OUT_MEM_OFF);
        for (size_t i = wbeg + (size_t)lblk * 256 + threadIdx.x; i < wend;
             i += (size_t)BPP * 256)
            __stcs(dst + i, __ldg(src + i));
    }

    // ---- gather bin (grp_g+15)%16 (previous group's window -> L2 hits) ----
    const unsigned bin = (grp_g + NPHASE - 1) & (NPHASE - 1);
    const unsigned count = min(g_bcnt[bin], (unsigned)CAPB);
    const size_t bin_base = (size_t)bin * CAPB;

    float lsum = 0.0f;
    unsigned base = lblk * 32u;
    do {
        const unsigned e  = base + (unsigned)(warp * 4 + grp);
        const bool     ok = e < count;
        const unsigned ee = ok ? e : 0u;      // stale slots hold valid packings

        const uint2 ent    = __ldg(&g_ent[bin_base + ee]);
        const unsigned row = ent.x & 0xFFFFFu;
        const unsigned b   = ent.x >> 20;
        const unsigned k   = ent.y;

        const float4* w4 = (const float4*)(mem + (size_t)row * NDIM);
        const float4* x4 = (const float4*)(x + b * NDIM);
        const float4* z4 = (const float4*)(z + b * NDIM);

        float dx = 0.0f, dz = 0.0f;
        #pragma unroll
        for (int j = 0; j < 4; j++) {
            const float4 w  = __ldg(w4 + li + 8 * j);
            const float4 xv = __ldg(x4 + li + 8 * j);
            const float4 zv = __ldg(z4 + li + 8 * j);
            dx += w.x * xv.x + w.y * xv.y + w.z * xv.z + w.w * xv.w;
            dz += w.x * zv.x + w.y * zv.y + w.z * zv.z + w.w * zv.w;
        }
        #pragma unroll
        for (int off = 4; off; off >>= 1) {
            dx += __shfl_xor_sync(0xffffffffu, dx, off);
            dz += __shfl_xor_sync(0xffffffffu, dz, off);
        }

        if (li == 0 && ok) {
            const float lx = expf(dx * INV_T);
            const float lz = expf(dz * INV_T);
            out[(size_t)b * KP1 + k]              = lx;
            out[OUT_LZ_OFF + (size_t)b * KP1 + k] = lz;
            lsum += lx;
        }
        base += 32u;
    } while (lblk == BPP - 1 && base < count);   // tail absorber (uniform)

    // ---- block reduction into g_sum ----
    float s = lsum;                          // nonzero only on lanes 0,8,16,24
    s += __shfl_xor_sync(0xffffffffu, s, 8);
    s += __shfl_xor_sync(0xffffffffu, s, 16);
    if (lane == 0) s_part[warp] = (double)s;
    __syncthreads();
    if (threadIdx.x == 0) {
        double acc = 0.0;
        #pragma unroll
        for (int i = 0; i < 8; i++) acc += s_part[i];
        if (acc != 0.0) atomicAdd(&g_sum, acc);
    }

#if __CUDA_ARCH__ >= 900
    cudaTriggerProgrammaticLaunchCompletion();
#endif
}

// ---------------------------------------------------------------------------
// Pass 3: scale lx/lz by 1/Z0 (MLP=4), 16-row EMA scatter, replay reset.
// ---------------------------------------------------------------------------
__global__ void __launch_bounds__(256) k_finish(
    const float* __restrict__ x, const float* __restrict__ mem,
    const int* __restrict__ y, float* __restrict__ out)
{
#if __CUDA_ARCH__ >= 900
    cudaGridDependencySynchronize();   // g_sum + all k_main stores visible
#endif

    __shared__ float s_inv;
    if (threadIdx.x == 0) {
        const double z0 = g_sum / (double)LOGITS * (double)NDATA;
        s_inv = (float)(1.0 / z0);
    }
    __syncthreads();
    const float inv = s_inv;

    if (blockIdx.x < 2) {
        const int warp = threadIdx.x >> 5;
        const int lane = threadIdx.x & 31;
        const int b    = blockIdx.x * 8 + warp;   // 0..15

        const int row = __ldg(&y[b]);
        const float4 m  = __ldg((const float4*)(mem + (size_t)row * NDIM) + lane);
        const float4 xv = __ldg((const float4*)(x + b * NDIM) + lane);

        float4 w;
        w.x = EMA_M * m.x + (1.0f - EMA_M) * xv.x;
        w.y = EMA_M * m.y + (1.0f - EMA_M) * xv.y;
        w.z = EMA_M * m.z + (1.0f - EMA_M) * xv.z;
        w.w = EMA_M * m.w + (1.0f - EMA_M) * xv.w;

        float nrm = w.x * w.x + w.y * w.y + w.z * w.z + w.w * w.w;
        #pragma unroll
        for (int off = 16; off; off >>= 1)
            nrm += __shfl_xor_sync(0xffffffffu, nrm, off);
        const float rinv = rsqrtf(nrm);

        float4 o;
        o.x = w.x * rinv; o.y = w.y * rinv; o.z = w.z * rinv; o.w = w.w * rinv;
        ((float4*)(out + OUT_MEM_OFF + (size_t)row * NDIM))[lane] = o;
    }

    {
        float4* p = (float4*)out;
        const size_t i0 = (size_t)blockIdx.x * 256 + threadIdx.x;
        const size_t j0 = i0;
        const size_t j1 = i0 + FIN_STRIDE;
        const size_t j2 = i0 + 2 * FIN_STRIDE;
        const size_t j3 = i0 + 3 * FIN_STRIDE;
        const bool   h3 = j3 < N4_SCALE;

        float4 v0 = p[j0];
        float4 v1 = p[j1];
        float4 v2 = p[j2];
        float4 v3;
        if (h3) v3 = p[j3];

        v0.x *= inv; v0.y *= inv; v0.z *= inv; v0.w *= inv;
        v1.x *= inv; v1.y *= inv; v1.z *= inv; v1.w *= inv;
        v2.x *= inv; v2.y *= inv; v2.z *= inv; v2.w *= inv;
        p[j0] = v0;
        p[j1] = v1;
        p[j2] = v2;
        if (h3) {
            v3.x *= inv; v3.y *= inv; v3.z *= inv; v3.w *= inv;
            p[j3] = v3;
        }
    }

    // replay-safe reset
    __syncthreads();
    if (threadIdx.x == 0) {
        __threadfence();
        const unsigned prev = atomicAdd(&g_done, 1u);
        if (prev == FIN_BLKS - 1) {
            g_sum  = 0.0;
            g_done = 0u;
            #pragma unroll
            for (int i = 0; i < NPHASE; i++) g_bcnt[i] = 0u;
            __threadfence();
        }
    }
}

// ---------------------------------------------------------------------------
extern "C" void kernel_launch(void* const* d_in, const int* in_sizes, int n_in,
                              void* d_out, int out_size)
{
    const float* x   = (const float*)d_in[0];
    const float* z   = (const float*)d_in[1];
    const float* mem = (const float*)d_in[2];
    const int*   y   = (const int*)  d_in[3];
    const int*   idx = (const int*)  d_in[4];
    float*       out = (float*)d_out;

    (void)in_sizes; (void)n_in; (void)out_size;

    k_bin<<<BIN_BLKS, 256>>>(x, z, mem, y, idx, out);

    cudaLaunchAttribute attr[1];
    attr[0].id = cudaLaunchAttributeProgrammaticStreamSerialization;
    attr[0].val.programmaticStreamSerializationAllowed = 1;

    cudaLaunchConfig_t cfg1 = {};
    cfg1.gridDim  = dim3(TOTBLK, 1, 1);
    cfg1.blockDim = dim3(256, 1, 1);
    cfg1.attrs    = attr;
    cfg1.numAttrs = 1;
    cudaLaunchKernelEx(&cfg1, k_main, x, z, mem, out);

    cudaLaunchConfig_t cfg2 = {};
    cfg2.gridDim  = dim3(FIN_BLKS, 1, 1);
    cfg2.blockDim = dim3(256, 1, 1);
    cfg2.attrs    = attr;
    cfg2.numAttrs = 1;
    cudaLaunchKernelEx(&cfg2, k_finish, x, mem, y, out);
}

// round 15
// speedup vs baseline: 1.2792x; 1.2792x over previous
#include <cuda_runtime.h>
#include <math.h>

#define BSZ    16
#define KNEG   65536
#define KP1    65537u
#define NDIM   128
#define NDATA  1000000
#define INV_T  (1.0f / 0.07f)
#define EMA_M  0.5f

#define LOGITS       (BSZ * 65537)            // 1,048,592
#define NPHASE       16
#define RPP          (NDATA / NPHASE)         // 62,500 rows per phase window
#define PW4          ((size_t)RPP * NDIM / 4) // 2,000,000 float4 per window
#define BPP          2176                     // blocks per group
#define CPB          1600                     // copy-role blocks per group
#define GPB          (BPP - CPB)              // 576 gather-role blocks per group
#define TOTBLK       (NPHASE * BPP)           // 34,816
#define CAPB         131072                   // bin capacity (entries)

#define OUT_LZ_OFF   ((size_t)LOGITS)
#define OUT_MEM_OFF  ((size_t)2 * LOGITS)
#define N4_MEM       ((size_t)NDATA * NDIM / 4)     // 32,000,000
#define N4_SCALE     ((size_t)2 * LOGITS / 4)       // 524,296 (exact)

#define BIN_BLKS     4097u
#define FIN_BLKS     592u
#define FIN_STRIDE   ((size_t)FIN_BLKS * 256)

__device__ double   g_sum;              // zero-init; reset by k_finish each replay
__device__ unsigned g_done;
__device__ unsigned g_bcnt[NPHASE];     // per-phase entry counts
__device__ uint2    g_ent[(size_t)NPHASE * CAPB];   // 16 MB entry store

// ---------------------------------------------------------------------------
// Pass 1: bin every logit by memory-row phase.  Triggers PDL immediately so
// k_main's copy blocks (independent of bins) overlap with this pass.
// Entry = { (b<<20)|row , k }.
// ---------------------------------------------------------------------------
__global__ void __launch_bounds__(256) k_bin(
    const float* __restrict__ x, const float* __restrict__ z,
    const float* __restrict__ mem, const int* __restrict__ y,
    const int* __restrict__ idx, float* __restrict__ out)
{
#if __CUDA_ARCH__ >= 900
    cudaTriggerProgrammaticLaunchCompletion();   // let k_main schedule NOW
#endif

    __shared__ unsigned s_cnt[NPHASE];
    __shared__ unsigned s_base[NPHASE];
    if (threadIdx.x < NPHASE) s_cnt[threadIdx.x] = 0;
    __syncthreads();

    const unsigned t = blockIdx.x * 256u + threadIdx.x;
    const bool valid = t < (unsigned)LOGITS;

    unsigned b = 0, k = 0, bin = 0, lslot = 0;
    int row = 0;
    if (valid) {
        if (t < BSZ) { b = t; k = 0; row = __ldg(&y[b]); }
        else {
            const unsigned u = t - BSZ;
            b = u >> 16;
            k = (u & 65535u) + 1u;
            row = __ldg(&idx[u]);
        }
        bin   = (unsigned)row / RPP;
        lslot = atomicAdd(&s_cnt[bin], 1u);
    }
    __syncthreads();
    if (threadIdx.x < NPHASE && s_cnt[threadIdx.x])
        s_base[threadIdx.x] = atomicAdd(&g_bcnt[threadIdx.x], s_cnt[threadIdx.x]);
    __syncthreads();

    if (valid) {
        const unsigned slot = s_base[bin] + lslot;
        if (slot < CAPB) {
            g_ent[(size_t)bin * CAPB + slot] = make_uint2((b << 20) | (unsigned)row, k);
        } else {
            // capacity overflow fallback (never for this input): compute inline
            const float* w = mem + (size_t)row * NDIM;
            float dx = 0.0f, dz = 0.0f;
            for (int i = 0; i < NDIM; i++) {
                const float wv = __ldg(w + i);
                dx += wv * __ldg(&x[b * NDIM + i]);
                dz += wv * __ldg(&z[b * NDIM + i]);
            }
            const float lx = expf(dx * INV_T);
            const float lz = expf(dz * INV_T);
            out[(size_t)b * KP1 + k]              = lx;
            out[OUT_LZ_OFF + (size_t)b * KP1 + k] = lz;
            atomicAdd(&g_sum, (double)lx);
        }
    }
}

// ---------------------------------------------------------------------------
// Pass 2 (intra-group role split): in group g, blocks [0,CPB) stream-copy
// window g (cached loads seed L2); blocks [CPB,BPP) — scheduled after them —
// gather bin g's entries against the freshly copied, L2-hot window.
// ---------------------------------------------------------------------------
__global__ void __launch_bounds__(256) k_main(
    const float* __restrict__ x, const float* __restrict__ z,
    const float* __restrict__ mem, float* __restrict__ out)
{
    const unsigned grp_g = blockIdx.x / BPP;       // 0..15
    const unsigned lblk  = blockIdx.x - grp_g * BPP;

    if (lblk < CPB) {
        // ---------------- copy role (no dependency on k_bin) ----------------
        const size_t wbeg = (size_t)grp_g * PW4;
        const size_t wend = wbeg + PW4;
        const float4* src = (const float4*)mem;
        float4*       dst = (float4*)(out + OUT_MEM_OFF);
        for (size_t i = wbeg + (size_t)lblk * 256 + threadIdx.x; i < wend;
             i += (size_t)CPB * 256)
            __stcs(dst + i, __ldg(src + i));
        return;
    }

    // ---------------- gather role ----------------
#if __CUDA_ARCH__ >= 900
    cudaGridDependencySynchronize();   // k_bin entries visible (long done by now)
#endif

    const unsigned gblk = lblk - CPB;              // 0..GPB-1
    const int warp = threadIdx.x >> 5;
    const int lane = threadIdx.x & 31;
    const int grp  = lane >> 3;
    const int li   = lane & 7;

    __shared__ double s_part[8];

    const unsigned bin   = grp_g;
    const unsigned count = min(g_bcnt[bin], (unsigned)CAPB);
    const size_t bin_base = (size_t)bin * CAPB;

    float lsum = 0.0f;
    for (unsigned base = gblk * 32u; base < count; base += GPB * 32u) {
        const unsigned e  = base + (unsigned)(warp * 4 + grp);
        const bool     ok = e < count;
        const unsigned ee = ok ? e : 0u;      // stale slots hold valid packings

        const uint2 ent    = __ldg(&g_ent[bin_base + ee]);
        const unsigned row = ent.x & 0xFFFFFu;
        const unsigned b   = ent.x >> 20;
        const unsigned k   = ent.y;

        const float4* w4 = (const float4*)(mem + (size_t)row * NDIM);
        const float4* x4 = (const float4*)(x + b * NDIM);
        const float4* z4 = (const float4*)(z + b * NDIM);

        float dx = 0.0f, dz = 0.0f;
        #pragma unroll
        for (int j = 0; j < 4; j++) {
            const float4 w  = __ldg(w4 + li + 8 * j);
            const float4 xv = __ldg(x4 + li + 8 * j);
            const float4 zv = __ldg(z4 + li + 8 * j);
            dx += w.x * xv.x + w.y * xv.y + w.z * xv.z + w.w * xv.w;
            dz += w.x * zv.x + w.y * zv.y + w.z * zv.z + w.w * zv.w;
        }
        #pragma unroll
        for (int off = 4; off; off >>= 1) {
            dx += __shfl_xor_sync(0xffffffffu, dx, off);
            dz += __shfl_xor_sync(0xffffffffu, dz, off);
        }

        if (li == 0 && ok) {
            const float lx = expf(dx * INV_T);
            const float lz = expf(dz * INV_T);
            out[(size_t)b * KP1 + k]              = lx;
            out[OUT_LZ_OFF + (size_t)b * KP1 + k] = lz;
            lsum += lx;
        }
    }

    // ---- block reduction into g_sum ----
    float s = lsum;                          // nonzero only on lanes 0,8,16,24
    s += __shfl_xor_sync(0xffffffffu, s, 8);
    s += __shfl_xor_sync(0xffffffffu, s, 16);
    if (lane == 0) s_part[warp] = (double)s;
    __syncthreads();
    if (threadIdx.x == 0) {
        double acc = 0.0;
        #pragma unroll
        for (int i = 0; i < 8; i++) acc += s_part[i];
        if (acc != 0.0) atomicAdd(&g_sum, acc);
    }
}

// ---------------------------------------------------------------------------
// Pass 3: scale lx/lz by 1/Z0 (MLP=4), 16-row EMA scatter, replay reset.
// ---------------------------------------------------------------------------
__global__ void __launch_bounds__(256) k_finish(
    const float* __restrict__ x, const float* __restrict__ mem,
    const int* __restrict__ y, float* __restrict__ out)
{
#if __CUDA_ARCH__ >= 900
    cudaGridDependencySynchronize();   // g_sum + all k_main stores visible
#endif

    __shared__ float s_inv;
    if (threadIdx.x == 0) {
        const double z0 = g_sum / (double)LOGITS * (double)NDATA;
        s_inv = (float)(1.0 / z0);
    }
    __syncthreads();
    const float inv = s_inv;

    if (blockIdx.x < 2) {
        const int warp = threadIdx.x >> 5;
        const int lane = threadIdx.x & 31;
        const int b    = blockIdx.x * 8 + warp;   // 0..15

        const int row = __ldg(&y[b]);
        const float4 m  = __ldg((const float4*)(mem + (size_t)row * NDIM) + lane);
        const float4 xv = __ldg((const float4*)(x + b * NDIM) + lane);

        float4 w;
        w.x = EMA_M * m.x + (1.0f - EMA_M) * xv.x;
        w.y = EMA_M * m.y + (1.0f - EMA_M) * xv.y;
        w.z = EMA_M * m.z + (1.0f - EMA_M) * xv.z;
        w.w = EMA_M * m.w + (1.0f - EMA_M) * xv.w;

        float nrm = w.x * w.x + w.y * w.y + w.z * w.z + w.w * w.w;
        #pragma unroll
        for (int off = 16; off; off >>= 1)
            nrm += __shfl_xor_sync(0xffffffffu, nrm, off);
        const float rinv = rsqrtf(nrm);

        float4 o;
        o.x = w.x * rinv; o.y = w.y * rinv; o.z = w.z * rinv; o.w = w.w * rinv;
        ((float4*)(out + OUT_MEM_OFF + (size_t)row * NDIM))[lane] = o;
    }

    {
        float4* p = (float4*)out;
        const size_t i0 = (size_t)blockIdx.x * 256 + threadIdx.x;
        const size_t j0 = i0;
        const size_t j1 = i0 + FIN_STRIDE;
        const size_t j2 = i0 + 2 * FIN_STRIDE;
        const size_t j3 = i0 + 3 * FIN_STRIDE;
        const bool   h3 = j3 < N4_SCALE;

        float4 v0 = p[j0];
        float4 v1 = p[j1];
        float4 v2 = p[j2];
        float4 v3;
        if (h3) v3 = p[j3];

        v0.x *= inv; v0.y *= inv; v0.z *= inv; v0.w *= inv;
        v1.x *= inv; v1.y *= inv; v1.z *= inv; v1.w *= inv;
        v2.x *= inv; v2.y *= inv; v2.z *= inv; v2.w *= inv;
        p[j0] = v0;
        p[j1] = v1;
        p[j2] = v2;
        if (h3) {
            v3.x *= inv; v3.y *= inv; v3.z *= inv; v3.w *= inv;
            p[j3] = v3;
        }
    }

    // replay-safe reset
    __syncthreads();
    if (threadIdx.x == 0) {
        __threadfence();
        const unsigned prev = atomicAdd(&g_done, 1u);
        if (prev == FIN_BLKS - 1) {
            g_sum  = 0.0;
            g_done = 0u;
            #pragma unroll
            for (int i = 0; i < NPHASE; i++) g_bcnt[i] = 0u;
            __threadfence();
        }
    }
}

// ---------------------------------------------------------------------------
extern "C" void kernel_launch(void* const* d_in, const int* in_sizes, int n_in,
                              void* d_out, int out_size)
{
    const float* x   = (const float*)d_in[0];
    const float* z   = (const float*)d_in[1];
    const float* mem = (const float*)d_in[2];
    const int*   y   = (const int*)  d_in[3];
    const int*   idx = (const int*)  d_in[4];
    float*       out = (float*)d_out;

    (void)in_sizes; (void)n_in; (void)out_size;

    k_bin<<<BIN_BLKS, 256>>>(x, z, mem, y, idx, out);

    cudaLaunchAttribute attr[1];
    attr[0].id = cudaLaunchAttributeProgrammaticStreamSerialization;
    attr[0].val.programmaticStreamSerializationAllowed = 1;

    cudaLaunchConfig_t cfg1 = {};
    cfg1.gridDim  = dim3(TOTBLK, 1, 1);
    cfg1.blockDim = dim3(256, 1, 1);
    cfg1.attrs    = attr;
    cfg1.numAttrs = 1;
    cudaLaunchKernelEx(&cfg1, k_main, x, z, mem, out);

    cudaLaunchConfig_t cfg2 = {};
    cfg2.gridDim  = dim3(FIN_BLKS, 1, 1);
    cfg2.blockDim = dim3(256, 1, 1);
    cfg2.attrs    = attr;
    cfg2.numAttrs = 1;
    cudaLaunchKernelEx(&cfg2, k_finish, x, mem, y, out);
}